// round 1
// baseline (speedup 1.0000x reference)
#include <cuda_runtime.h>

// x: [8, 64, 64, 64, 64] fp32. Per (b,c) slice of 64^3:
//   s = sum over 2x2x2 windows of (max(window) + mean(window))
//   pooled[b,c] = s^2 ;  out[b,c] = pooled / max(||pooled[b,:]||_2, 1e-12)

#define CH 4                       // chunks along h2 (32 h2 rows -> 8 per chunk)
#define NBC 512                    // 8*64 (b,c) pairs

__device__ float g_partial[NBC * CH];

__global__ __launch_bounds__(256) void pool_reduce_kernel(const float* __restrict__ x) {
    const int bc    = blockIdx.x / CH;
    const int chunk = blockIdx.x % CH;
    const float* __restrict__ base = x + (size_t)bc * (64 * 64 * 64);

    const int tid = threadIdx.x;       // 256 threads
    const int tx  = tid & 15;          // d-group: covers d = 4*tx .. 4*tx+3 (two d2 windows)
    const int g   = tid >> 4;          // 0..15: strides over (h2, w2) pairs

    float acc = 0.0f;

    // 256 (h2,w2) pairs in this chunk: h2 in [chunk*8, chunk*8+8), w2 in [0,32)
    #pragma unroll 4
    for (int p = g; p < 256; p += 16) {
        const int h2 = (chunk << 3) + (p >> 5);
        const int w2 = p & 31;
        const float* r = base + ((size_t)(2 * h2) * 4096) + ((2 * w2) * 64) + (tx << 2);

        const float4 a = *(const float4*)(r);                 // (2h2,   2w2  )
        const float4 b = *(const float4*)(r + 64);            // (2h2,   2w2+1)
        const float4 c = *(const float4*)(r + 4096);          // (2h2+1, 2w2  )
        const float4 d = *(const float4*)(r + 4096 + 64);     // (2h2+1, 2w2+1)

        // window d2 = 2*tx  -> .x,.y of all four rows
        float m0 = fmaxf(fmaxf(fmaxf(a.x, a.y), fmaxf(b.x, b.y)),
                         fmaxf(fmaxf(c.x, c.y), fmaxf(d.x, d.y)));
        // window d2 = 2*tx+1 -> .z,.w
        float m1 = fmaxf(fmaxf(fmaxf(a.z, a.w), fmaxf(b.z, b.w)),
                         fmaxf(fmaxf(c.z, c.w), fmaxf(d.z, d.w)));

        float sum = (a.x + a.y + a.z + a.w) + (b.x + b.y + b.z + b.w)
                  + (c.x + c.y + c.z + c.w) + (d.x + d.y + d.z + d.w);

        acc += m0 + m1 + sum * 0.125f;
    }

    // block tree-reduce over 256 threads
    __shared__ float sred[256];
    sred[tid] = acc;
    __syncthreads();
    #pragma unroll
    for (int off = 128; off > 0; off >>= 1) {
        if (tid < off) sred[tid] += sred[tid + off];
        __syncthreads();
    }
    if (tid == 0) g_partial[bc * CH + chunk] = sred[0];
}

__global__ __launch_bounds__(64) void finalize_kernel(float* __restrict__ out) {
    __shared__ float sp[64];
    const int b = blockIdx.x;   // 0..7
    const int c = threadIdx.x;  // 0..63

    float s = 0.0f;
    #pragma unroll
    for (int k = 0; k < CH; k++) s += g_partial[(b * 64 + c) * CH + k];

    const float pooled = s * s;
    sp[c] = pooled * pooled;
    __syncthreads();
    #pragma unroll
    for (int off = 32; off > 0; off >>= 1) {
        if (c < off) sp[c] += sp[c + off];
        __syncthreads();
    }
    const float norm = fmaxf(sqrtf(sp[0]), 1e-12f);
    out[b * 64 + c] = pooled / norm;
}

extern "C" void kernel_launch(void* const* d_in, const int* in_sizes, int n_in,
                              void* d_out, int out_size) {
    const float* x = (const float*)d_in[0];
    float* out = (float*)d_out;
    pool_reduce_kernel<<<NBC * CH, 256>>>(x);
    finalize_kernel<<<8, 64>>>(out);
}

// round 2
// speedup vs baseline: 1.0034x; 1.0034x over previous
#include <cuda_runtime.h>

// x: [8, 64, 64, 64, 64] fp32. Per (b,c) slice of 64^3:
//   s = sum over 2x2x2 windows of (max(window) + mean(window))
//   pooled[b,c] = s^2 ;  out[b,c] = pooled / max(||pooled[b,:]||_2, 1e-12)
//
// Single fused kernel: 512 blocks (one per (b,c) slice, 1 MiB each) — single
// wave on 148 SMs, no ragged tail. Last block (atomic ticket) does the
// normalize epilogue, eliminating the second launch's ~4 us overhead.

#define NBC 512   // 8*64 (b,c) pairs == gridDim.x

__device__ float g_partial[NBC];
__device__ unsigned int g_counter = 0;

__global__ __launch_bounds__(256) void fused_pool_kernel(const float* __restrict__ x,
                                                         float* __restrict__ out) {
    const int bc = blockIdx.x;
    const float* __restrict__ base = x + (size_t)bc * (64 * 64 * 64);

    const int tid = threadIdx.x;       // 256 threads
    const int tx  = tid & 15;          // d-group: d = 4*tx .. 4*tx+3 (two d2 windows)
    const int g   = tid >> 4;          // 0..15: strides over (h2, w2) pairs

    float acc = 0.0f;

    // 1024 (h2,w2) pairs per slice: h2 in [0,32), w2 in [0,32)
    #pragma unroll 4
    for (int p = g; p < 1024; p += 16) {
        const int h2 = p >> 5;
        const int w2 = p & 31;
        const float* r = base + ((size_t)(2 * h2) * 4096) + ((2 * w2) * 64) + (tx << 2);

        const float4 a = *(const float4*)(r);                 // (2h2,   2w2  )
        const float4 b = *(const float4*)(r + 64);            // (2h2,   2w2+1)
        const float4 c = *(const float4*)(r + 4096);          // (2h2+1, 2w2  )
        const float4 d = *(const float4*)(r + 4096 + 64);     // (2h2+1, 2w2+1)

        // window d2 = 2*tx  -> .x,.y of all four rows
        float m0 = fmaxf(fmaxf(fmaxf(a.x, a.y), fmaxf(b.x, b.y)),
                         fmaxf(fmaxf(c.x, c.y), fmaxf(d.x, d.y)));
        // window d2 = 2*tx+1 -> .z,.w
        float m1 = fmaxf(fmaxf(fmaxf(a.z, a.w), fmaxf(b.z, b.w)),
                         fmaxf(fmaxf(c.z, c.w), fmaxf(d.z, d.w)));

        float sum = (a.x + a.y + a.z + a.w) + (b.x + b.y + b.z + b.w)
                  + (c.x + c.y + c.z + c.w) + (d.x + d.y + d.z + d.w);

        acc += m0 + m1 + sum * 0.125f;
    }

    // block tree-reduce over 256 threads
    __shared__ float sred[256];
    __shared__ int s_islast;
    sred[tid] = acc;
    __syncthreads();
    #pragma unroll
    for (int off = 128; off > 0; off >>= 1) {
        if (tid < off) sred[tid] += sred[tid + off];
        __syncthreads();
    }

    if (tid == 0) {
        g_partial[bc] = sred[0];
        __threadfence();                          // publish partial before ticket
        unsigned int old = atomicAdd(&g_counter, 1u);
        s_islast = (old == (unsigned int)(gridDim.x - 1));
    }
    __syncthreads();
    if (!s_islast) return;

    // ---- last block: finalize (all 512 partials are visible) ----
    __threadfence();
    __shared__ float s_norm[8];

    const int w = tid >> 5;            // warp 0..7 -> batch b
    const int l = tid & 31;            // lane -> channels l and l+32

    const float s0 = g_partial[w * 64 + l];
    const float s1 = g_partial[w * 64 + l + 32];
    const float p0 = s0 * s0;
    const float p1 = s1 * s1;

    float q = p0 * p0 + p1 * p1;
    #pragma unroll
    for (int off = 16; off > 0; off >>= 1)
        q += __shfl_xor_sync(0xFFFFFFFFu, q, off);

    if (l == 0) s_norm[w] = fmaxf(sqrtf(q), 1e-12f);
    __syncthreads();

    const float inv = 1.0f / s_norm[w];
    out[w * 64 + l]      = p0 * inv;
    out[w * 64 + l + 32] = p1 * inv;

    if (tid == 0) g_counter = 0;       // reset for next graph replay
}

extern "C" void kernel_launch(void* const* d_in, const int* in_sizes, int n_in,
                              void* d_out, int out_size) {
    const float* x = (const float*)d_in[0];
    float* out = (float*)d_out;
    fused_pool_kernel<<<NBC, 256>>>(x, out);
}